// round 15
// baseline (speedup 1.0000x reference)
#include <cuda_runtime.h>
#include <cuda_bf16.h>
#include <math.h>
#include <cstdint>

typedef unsigned long long ull;

#define T_ 1024
#define B_ 16
#define E_ 1024
#define H_ 512
#define C_ 1024
#define L_ 6
#define M_ (T_*B_)
#define NG 4096
#define KI 1024
#define KC_ (5*E_)              // 5120 conv GEMM K

// ------------------------ device scratch ------------------------
__device__ float g_xbuf[2][(size_t)M_*C_];       // fp32 activations (layer-3 out / classifier in)
__device__ float g_G[(size_t)M_*NG];             // input-projected gates [m][4096]
__device__ unsigned short g_Xhi[(size_t)M_*KI];  // bf16 hi plane of activations
__device__ unsigned short g_Xlo[(size_t)M_*KI];  // bf16 lo plane
__device__ unsigned short g_Whi[3][(size_t)NG*KI]; // bf16 hi of wih ([n][k] layout)
__device__ unsigned short g_Wlo[3][(size_t)NG*KI];
__device__ unsigned short g_Ehi[(size_t)B_*T_*E_]; // bf16 hi of embeddings
__device__ unsigned short g_Elo[(size_t)B_*T_*E_];
__device__ unsigned short g_CWhi[(size_t)C_*KC_];  // conv w planes, [c][dk*1024+e]
__device__ unsigned short g_CWlo[(size_t)C_*KC_];
__device__ float g_biasG[3][NG];
__device__ float g_bnA[C_], g_bnB[C_];
__device__ unsigned short g_hHi[2][2][H_*B_];    // h bf16 hi plane, [b*512+j]
__device__ unsigned short g_hLo[2][2][H_*B_];    // h bf16 lo plane
__device__ unsigned g_cnt[2][T_];
__device__ float g_logits[M_*L_];

// ------------------------ helpers ------------------------
__device__ __forceinline__ float sigf(float x){ return 1.f/(1.f + expf(-x)); }
__device__ __forceinline__ float sigf_fast(float x){ return __fdividef(1.f, 1.f + __expf(-x)); }
__device__ __forceinline__ float tanh_fast(float x){ return 1.f - __fdividef(2.f, __expf(2.f*x) + 1.f); }

__device__ __forceinline__ void split_bf(float v, unsigned short& h, unsigned short& l){
    __nv_bfloat16 hb = __float2bfloat16(v);
    h = __bfloat16_as_ushort(hb);
    l = __bfloat16_as_ushort(__float2bfloat16(v - __bfloat162float(hb)));
}

__device__ __forceinline__ unsigned smem_u32(const void* p){
    unsigned a; asm("{ .reg .u64 t; cvta.to.shared.u64 t, %1; cvt.u32.u64 %0, t; }" : "=r"(a) : "l"(p));
    return a;
}

#define LDSM4(r, a) \
    asm volatile("ldmatrix.sync.aligned.m8n8.x4.shared.b16 {%0,%1,%2,%3}, [%4];" \
        : "=r"((r)[0]),"=r"((r)[1]),"=r"((r)[2]),"=r"((r)[3]) : "r"(a))

#define LDSM2(r, a) \
    asm volatile("ldmatrix.sync.aligned.m8n8.x2.shared.b16 {%0,%1}, [%2];" \
        : "=r"((r)[0]),"=r"((r)[1]) : "r"(a))

#define MMA16816(dd, A, b0, b1) \
    asm volatile("mma.sync.aligned.m16n8k16.row.col.f32.bf16.bf16.f32 " \
        "{%0,%1,%2,%3}, {%4,%5,%6,%7}, {%8,%9}, {%0,%1,%2,%3};" \
        : "+f"((dd)[0]),"+f"((dd)[1]),"+f"((dd)[2]),"+f"((dd)[3]) \
        : "r"((A)[0]),"r"((A)[1]),"r"((A)[2]),"r"((A)[3]), "r"(b0),"r"(b1))

// ------------------------ pack / convert kernels ------------------------
__global__ void k_cvt_e(const float* __restrict__ emb){
    size_t idx = (size_t)blockIdx.x*256 + threadIdx.x;
    float v = emb[idx];
    unsigned short h, l; split_bf(v, h, l);
    g_Ehi[idx] = h;
    g_Elo[idx] = l;
}

__global__ void k_cvt_cw(const float* __restrict__ cw){
    size_t idx = (size_t)blockIdx.x*256 + threadIdx.x;
    int c  = (int)(idx / KC_);
    int kk = (int)(idx - (size_t)c*KC_);
    int dk = kk >> 10, e = kk & 1023;
    float v = cw[((size_t)c*E_ + e)*5 + dk];
    unsigned short h, l; split_bf(v, h, l);
    g_CWhi[idx] = h;
    g_CWlo[idx] = l;
}

__global__ void k_cvt_w(const float* __restrict__ wih){
    size_t idx = (size_t)blockIdx.x*256 + threadIdx.x;
    float v = wih[idx];
    unsigned short h, l; split_bf(v, h, l);
    ((unsigned short*)g_Whi)[idx] = h;
    ((unsigned short*)g_Wlo)[idx] = l;
}

__global__ void k_pack_small(const float* __restrict__ bih, const float* __restrict__ bhh,
                             const float* __restrict__ gamma, const float* __restrict__ beta,
                             const float* __restrict__ mean, const float* __restrict__ var,
                             const float* __restrict__ convb){
    int idx = blockIdx.x*256 + threadIdx.x;
    if (idx < 3*NG){
        int l = idx / NG; int n = idx - l*NG;
        int dir = n >> 11, r = n & 2047;
        int src = (l*2+dir)*2048 + r;
        ((float*)g_biasG)[idx] = bih[src] + bhh[src];
    }
    if (idx < C_){
        float s = gamma[idx] * rsqrtf(var[idx] + 1e-5f);
        g_bnA[idx] = s;
        g_bnB[idx] = s*convb[idx] + beta[idx] - mean[idx]*s;
    }
}

__global__ void k_reset(){
    int idx = blockIdx.x*256 + threadIdx.x;       // 128 blocks x 256 = 32768
    if (idx < 2*2*H_*B_){
        ((unsigned short*)g_hHi)[idx] = 0;
        ((unsigned short*)g_hLo)[idx] = 0;
    }
    if (idx < 2*T_) ((unsigned*)g_cnt)[idx] = 0u;
}

// ------------------------ shared HMMA tile layout ------------------------
#define PLANE_B 10240            // 128*80
#define STAGE_B (4*PLANE_B)      // 40960
#define GT_SMEM (2*STAGE_B)      // 81920

// ------------------------ split-bf16 HMMA conv GEMM + BN + ReLU ------------------------
__global__ void __launch_bounds__(256) k_convT(){
    extern __shared__ char smem[];
    unsigned sbase = smem_u32(smem);
    int tid = threadIdx.x;
    int wid = tid >> 5, lane = tid & 31;
    int m0 = blockIdx.y*128, n0 = blockIdx.x*128;

    auto prefetch = [&](int kc, int stg){
        unsigned sb = sbase + stg*STAGE_B;
        int dk = (kc*32) >> 10;
        int e_base = (kc*32) & 1023;
        #pragma unroll
        for (int it = 0; it < 8; ++it){
            int i = it*256 + tid;
            int p = i >> 9, rem = i & 511;
            int row = rem >> 2, c = rem & 3;
            unsigned sa = sb + p*PLANE_B + row*80 + c*16;
            if (p < 2){
                int m = m0 + row;
                int t = m >> 4, b = m & 15;
                int tp = t + dk - 2;
                const unsigned short* base = (p == 0) ? g_Ehi : g_Elo;
                const void* ga = base + ((size_t)b*1024 + tp)*1024 + e_base + c*8;
                unsigned sz = ((unsigned)tp < 1024u) ? 16u : 0u;
                asm volatile("cp.async.cg.shared.global [%0], [%1], 16, %2;"
                             :: "r"(sa), "l"(ga), "r"(sz) : "memory");
            } else {
                const unsigned short* base = (p == 2) ? g_CWhi : g_CWlo;
                const void* ga = base + (size_t)(n0 + row)*KC_ + kc*32 + c*8;
                asm volatile("cp.async.cg.shared.global [%0], [%1], 16;"
                             :: "r"(sa), "l"(ga) : "memory");
            }
        }
        asm volatile("cp.async.commit_group;" ::: "memory");
    };

    int wm = wid >> 1, wn = wid & 1;
    float d[2][8][4];
    #pragma unroll
    for (int mi=0;mi<2;++mi)
        #pragma unroll
        for (int ni=0;ni<8;++ni)
            #pragma unroll
            for (int q=0;q<4;++q) d[mi][ni][q] = 0.f;

    prefetch(0, 0);

    for (int kt = 0; kt < KC_/32; ++kt){
        int stg = kt & 1;
        asm volatile("cp.async.wait_group 0;" ::: "memory");
        __syncthreads();
        if (kt + 1 < KC_/32) prefetch(kt + 1, stg ^ 1);

        unsigned sb  = sbase + stg*STAGE_B;
        unsigned aHi = sb,            aLo = sb + PLANE_B;
        unsigned bHi = sb + 2*PLANE_B, bLo = sb + 3*PLANE_B;

        #pragma unroll
        for (int kh = 0; kh < 2; ++kh){
            unsigned Ah[2][4], Al[2][4];
            #pragma unroll
            for (int mi = 0; mi < 2; ++mi){
                int row = wm*32 + mi*16 + (lane & 15);
                int ch  = kh*2 + (lane >> 4);
                unsigned off = row*80 + ch*16;
                LDSM4(Ah[mi], aHi + off);
                LDSM4(Al[mi], aLo + off);
            }
            unsigned Bh[4][4], Bl[4][4];
            #pragma unroll
            for (int pr = 0; pr < 4; ++pr){
                int row = wn*64 + pr*16 + (lane & 7) + ((lane >> 4) << 3);
                int ch  = kh*2 + ((lane >> 3) & 1);
                unsigned off = row*80 + ch*16;
                LDSM4(Bh[pr], bHi + off);
                LDSM4(Bl[pr], bLo + off);
            }
            #pragma unroll
            for (int mi = 0; mi < 2; ++mi){
                #pragma unroll
                for (int pr = 0; pr < 4; ++pr){
                    MMA16816(d[mi][2*pr],   Ah[mi], Bh[pr][0], Bh[pr][1]);
                    MMA16816(d[mi][2*pr],   Ah[mi], Bl[pr][0], Bl[pr][1]);
                    MMA16816(d[mi][2*pr],   Al[mi], Bh[pr][0], Bh[pr][1]);
                    MMA16816(d[mi][2*pr+1], Ah[mi], Bh[pr][2], Bh[pr][3]);
                    MMA16816(d[mi][2*pr+1], Ah[mi], Bl[pr][2], Bl[pr][3]);
                    MMA16816(d[mi][2*pr+1], Al[mi], Bh[pr][2], Bh[pr][3]);
                }
            }
        }
    }

    int qr = lane >> 2, qc = lane & 3;
    #pragma unroll
    for (int mi = 0; mi < 2; ++mi){
        #pragma unroll
        for (int ni = 0; ni < 8; ++ni){
            int col = n0 + wn*64 + ni*8 + qc*2;
            float2 A = *(const float2*)&g_bnA[col];
            float2 Bb = *(const float2*)&g_bnB[col];
            int r0 = m0 + wm*32 + mi*16 + qr;
            float v00 = fmaxf(d[mi][ni][0]*A.x + Bb.x, 0.f);
            float v01 = fmaxf(d[mi][ni][1]*A.y + Bb.y, 0.f);
            float v10 = fmaxf(d[mi][ni][2]*A.x + Bb.x, 0.f);
            float v11 = fmaxf(d[mi][ni][3]*A.y + Bb.y, 0.f);
            ushort2 h0, l0, h1, l1;
            split_bf(v00, h0.x, l0.x); split_bf(v01, h0.y, l0.y);
            split_bf(v10, h1.x, l1.x); split_bf(v11, h1.y, l1.y);
            *(ushort2*)&g_Xhi[(size_t)r0*1024 + col]     = h0;
            *(ushort2*)&g_Xlo[(size_t)r0*1024 + col]     = l0;
            *(ushort2*)&g_Xhi[(size_t)(r0+8)*1024 + col] = h1;
            *(ushort2*)&g_Xlo[(size_t)(r0+8)*1024 + col] = l1;
        }
    }
}

// ------------------------ mma.sync split-bf16 gate GEMM ------------------------
__global__ void __launch_bounds__(256) k_gate(int layer){
    extern __shared__ char smem[];
    unsigned sbase = smem_u32(smem);
    int tid = threadIdx.x;
    int wid = tid >> 5, lane = tid & 31;
    int m0 = blockIdx.y*128, n0 = blockIdx.x*128;

    const unsigned short* srcs[4] = {
        g_Xhi + (size_t)m0*1024,
        g_Xlo + (size_t)m0*1024,
        g_Whi[layer] + (size_t)n0*1024,
        g_Wlo[layer] + (size_t)n0*1024
    };

    auto prefetch = [&](int kc, int stg){
        unsigned sb = sbase + stg*STAGE_B;
        #pragma unroll
        for (int it = 0; it < 8; ++it){
            int i = it*256 + tid;
            int p = i >> 9, rem = i & 511;
            int row = rem >> 2, c = rem & 3;
            unsigned sa = sb + p*PLANE_B + row*80 + c*16;
            const void* ga = srcs[p] + (size_t)row*1024 + kc*32 + c*8;
            asm volatile("cp.async.cg.shared.global [%0], [%1], 16;" :: "r"(sa), "l"(ga) : "memory");
        }
        asm volatile("cp.async.commit_group;" ::: "memory");
    };

    int wm = wid >> 1, wn = wid & 1;
    float d[2][8][4];
    #pragma unroll
    for (int mi=0;mi<2;++mi)
        #pragma unroll
        for (int ni=0;ni<8;++ni)
            #pragma unroll
            for (int q=0;q<4;++q) d[mi][ni][q] = 0.f;

    prefetch(0, 0);

    for (int kt = 0; kt < 32; ++kt){
        int stg = kt & 1;
        asm volatile("cp.async.wait_group 0;" ::: "memory");
        __syncthreads();
        if (kt + 1 < 32) prefetch(kt + 1, stg ^ 1);

        unsigned sb  = sbase + stg*STAGE_B;
        unsigned aHi = sb,            aLo = sb + PLANE_B;
        unsigned bHi = sb + 2*PLANE_B, bLo = sb + 3*PLANE_B;

        #pragma unroll
        for (int kh = 0; kh < 2; ++kh){
            unsigned Ah[2][4], Al[2][4];
            #pragma unroll
            for (int mi = 0; mi < 2; ++mi){
                int row = wm*32 + mi*16 + (lane & 15);
                int ch  = kh*2 + (lane >> 4);
                unsigned off = row*80 + ch*16;
                LDSM4(Ah[mi], aHi + off);
                LDSM4(Al[mi], aLo + off);
            }
            unsigned Bh[4][4], Bl[4][4];
            #pragma unroll
            for (int pr = 0; pr < 4; ++pr){
                int row = wn*64 + pr*16 + (lane & 7) + ((lane >> 4) << 3);
                int ch  = kh*2 + ((lane >> 3) & 1);
                unsigned off = row*80 + ch*16;
                LDSM4(Bh[pr], bHi + off);
                LDSM4(Bl[pr], bLo + off);
            }
            #pragma unroll
            for (int mi = 0; mi < 2; ++mi){
                #pragma unroll
                for (int pr = 0; pr < 4; ++pr){
                    MMA16816(d[mi][2*pr],   Ah[mi], Bh[pr][0], Bh[pr][1]);
                    MMA16816(d[mi][2*pr],   Ah[mi], Bl[pr][0], Bl[pr][1]);
                    MMA16816(d[mi][2*pr],   Al[mi], Bh[pr][0], Bh[pr][1]);
                    MMA16816(d[mi][2*pr+1], Ah[mi], Bh[pr][2], Bh[pr][3]);
                    MMA16816(d[mi][2*pr+1], Ah[mi], Bl[pr][2], Bl[pr][3]);
                    MMA16816(d[mi][2*pr+1], Al[mi], Bh[pr][2], Bh[pr][3]);
                }
            }
        }
    }

    int qr = lane >> 2, qc = lane & 3;
    #pragma unroll
    for (int mi = 0; mi < 2; ++mi){
        #pragma unroll
        for (int ni = 0; ni < 8; ++ni){
            int col = n0 + wn*64 + ni*8 + qc*2;
            float2 bq = *(const float2*)&g_biasG[layer][col];
            int r0 = m0 + wm*32 + mi*16 + qr;
            float2 v0 = make_float2(d[mi][ni][0] + bq.x, d[mi][ni][1] + bq.y);
            *(float2*)&g_G[(size_t)r0*NG + col] = v0;
            float2 v1 = make_float2(d[mi][ni][2] + bq.x, d[mi][ni][3] + bq.y);
            *(float2*)&g_G[(size_t)(r0+8)*NG + col] = v1;
        }
    }
}

// ------------------------ persistent BiLSTM recurrence v3 (fixed: full K=512) ------------------------
// 64 blocks x 256 threads; warps 0-3 = fw (half 0), warps 4-7 = bw (half 1).
// Warp w of a half owns 8 gate-interleaved Whh rows: r=0..7 -> g=r>>1, j=j0+2w+(r&1).
// Full K=512 per warp: 32 k16-tiles, B-frags register-resident (Bh[32][2]+Bl[32][2]).
// Gate sums complete in-warp; 4x4 lane-quad xor-shuffle transposes gates so each
// lane owns one (b,j) cell; cell state c in a register. h exchanged via global
// bf16 hi/lo planes, staged with cp.async.
#define R3_PH(h)   ((h)*33280)
#define R3_SMEM    66560

__global__ void __launch_bounds__(256) k_recur3(const float* __restrict__ whh, int layer, int outparity,
                                                int writeF32, int writePlanes){
    extern __shared__ char smem[];
    unsigned sb = smem_u32(smem);
    int tid = threadIdx.x;
    int half = tid >> 7;                 // 0 = fw, 1 = bw
    int htid = tid & 127;
    int hwid = htid >> 5;                // warp within half, 0..3
    int lane = tid & 31;
    int dir = half;
    int bid = blockIdx.x;
    int j0 = bid*8;

    unsigned phBase = sb + R3_PH(half);  // in-loop: hi plane = phBase, lo = phBase + 16640

    // ---- stage Whh HI (gate-interleaved rows, 32 rows x 1040B flat) ----
    for (int i = htid; i < 4096; i += 128){     // 32 rows x 128 float4
        int row = i >> 7;
        int k4  = (i & 127) * 4;
        int w_ = row >> 3, r_ = row & 7;
        int g = r_ >> 1, jp = r_ & 1;
        float4 w = *(const float4*)&whh[(((size_t)(layer*2+dir))*2048 + g*512 + j0 + 2*w_ + jp)*512 + k4];
        unsigned short h0,l0,h1,l1,h2,l2,h3,l3;
        split_bf(w.x,h0,l0); split_bf(w.y,h1,l1); split_bf(w.z,h2,l2); split_bf(w.w,h3,l3);
        *(uint2*)(smem + R3_PH(half) + row*1040 + k4*2) =
            make_uint2((unsigned)h0 | ((unsigned)h1<<16), (unsigned)h2 | ((unsigned)h3<<16));
    }
    __syncthreads();
    unsigned Bh[32][2], Bl[32][2];
    {
        int rowB = hwid*8 + (lane & 7);
        int chB  = (lane >> 3) & 1;
        #pragma unroll
        for (int kt = 0; kt < 32; ++kt){
            unsigned off = rowB*1040 + kt*32 + chB*16;
            LDSM2(Bh[kt], phBase + off);
        }
    }
    __syncthreads();
    // ---- stage Whh LO (reuse region) ----
    for (int i = htid; i < 4096; i += 128){
        int row = i >> 7;
        int k4  = (i & 127) * 4;
        int w_ = row >> 3, r_ = row & 7;
        int g = r_ >> 1, jp = r_ & 1;
        float4 w = *(const float4*)&whh[(((size_t)(layer*2+dir))*2048 + g*512 + j0 + 2*w_ + jp)*512 + k4];
        unsigned short h0,l0,h1,l1,h2,l2,h3,l3;
        split_bf(w.x,h0,l0); split_bf(w.y,h1,l1); split_bf(w.z,h2,l2); split_bf(w.w,h3,l3);
        *(uint2*)(smem + R3_PH(half) + row*1040 + k4*2) =
            make_uint2((unsigned)l0 | ((unsigned)l1<<16), (unsigned)l2 | ((unsigned)l3<<16));
    }
    __syncthreads();
    {
        int rowB = hwid*8 + (lane & 7);
        int chB  = (lane >> 3) & 1;
        #pragma unroll
        for (int kt = 0; kt < 32; ++kt){
            unsigned off = rowB*1040 + kt*32 + chB*16;
            LDSM2(Bl[kt], phBase + off);
        }
    }
    __syncthreads();

    // ---- per-lane cell identity ----
    int qr = lane >> 2, qc = lane & 3;
    int bcell = qr + ((qc >> 1) << 3);          // batch 0..15
    int jpar = qc & 1;
    int jloc = j0 + 2*hwid + jpar;              // j within [0,512)
    int colG = dir*2048 + jloc;                 // + g*512 per gate
    float cReg = 0.f;
    float gReg[4];
    {
        int t0 = dir ? (T_-1) : 0;
        #pragma unroll
        for (int g2 = 0; g2 < 4; ++g2)
            gReg[g2] = g_G[(size_t)(t0*16 + bcell)*NG + colG + g2*512];
    }

    float* xout = g_xbuf[outparity];
    unsigned* cnt = &g_cnt[dir][0];
    int offA_row = (lane & 15)*1040 + (lane >> 4)*16;
    int barid = 1 + half;

    for (int s = 0; s < T_; ++s){
        // ---- stage h planes via cp.async (global -> smem, no unpack) ----
        const char* srcHi = (const char*)&g_hHi[dir][s & 1][0];
        const char* srcLo = (const char*)&g_hLo[dir][s & 1][0];
        #pragma unroll
        for (int it = 0; it < 16; ++it){
            int i = it*128 + htid;               // 0..2047 16B chunks
            int p = i >> 10;                     // 0 = hi, 1 = lo
            int rem = i & 1023;
            int b = rem >> 6, off = (rem & 63)*16;
            unsigned sa = phBase + p*16640 + b*1040 + off;
            const char* ga = (p ? srcLo : srcHi) + b*1024 + off;
            asm volatile("cp.async.cg.shared.global [%0], [%1], 16;" :: "r"(sa), "l"(ga) : "memory");
        }
        asm volatile("cp.async.commit_group;" ::: "memory");
        asm volatile("cp.async.wait_group 0;" ::: "memory");
        asm volatile("bar.sync %0, 128;" :: "r"(barid) : "memory");

        // ---- MMA: full K=512 (32 k16-tiles), gate sums complete in-warp ----
        float d[4] = {0.f, 0.f, 0.f, 0.f};
        #pragma unroll
        for (int kt = 0; kt < 32; ++kt){
            unsigned offA = offA_row + kt*32;
            unsigned Ah[4], Al[4];
            LDSM4(Ah, phBase + offA);
            LDSM4(Al, phBase + 16640 + offA);
            MMA16816(d, Ah, Bh[kt][0], Bh[kt][1]);
            MMA16816(d, Ah, Bl[kt][0], Bl[kt][1]);
            MMA16816(d, Al, Bh[kt][0], Bh[kt][1]);
        }

        // ---- 4x4 lane-quad xor transpose: gate[g] for this lane's cell ----
        float gate[4];
        gate[qc] = d[qc];
        #pragma unroll
        for (int m = 1; m < 4; ++m){
            int sel = qc ^ m;
            float pub = (sel == 0) ? d[0] : (sel == 1) ? d[1] : (sel == 2) ? d[2] : d[3];
            float got = __shfl_xor_sync(0xffffffffu, pub, m);
            gate[sel] = got;
        }

        // ---- prefetch next-step G ----
        float ng[4] = {0.f,0.f,0.f,0.f};
        if (s+1 < T_){
            int tn = dir ? (T_-2 - s) : (s+1);
            #pragma unroll
            for (int g2 = 0; g2 < 4; ++g2)
                ng[g2] = g_G[(size_t)(tn*16 + bcell)*NG + colG + g2*512];
        }

        // ---- cell update (registers only) ----
        float a0 = gReg[0] + gate[0];
        float a1 = gReg[1] + gate[1];
        float a2 = gReg[2] + gate[2];
        float a3 = gReg[3] + gate[3];
        cReg = sigf_fast(a1)*cReg + sigf_fast(a0)*tanh_fast(a2);
        float hval = sigf_fast(a3)*tanh_fast(cReg);
        unsigned short hh, hl;
        split_bf(hval, hh, hl);
        g_hHi[dir][(s+1)&1][bcell*512 + jloc] = hh;
        g_hLo[dir][(s+1)&1][bcell*512 + jloc] = hl;
        gReg[0] = ng[0]; gReg[1] = ng[1]; gReg[2] = ng[2]; gReg[3] = ng[3];

        asm volatile("bar.sync %0, 128;" :: "r"(barid) : "memory");
        if (htid == 0){
            asm volatile("red.release.gpu.global.add.u32 [%0], %1;"
                         :: "l"(&cnt[s]), "r"(1u) : "memory");
        }
        // deferred next-layer output stores (off the release chain)
        {
            int t2 = dir ? (T_-1 - s) : s;
            size_t mo = (size_t)(t2*16 + bcell)*1024 + dir*512 + jloc;
            if (writeF32) xout[mo] = hval;
            if (writePlanes){
                g_Xhi[mo] = hh;
                g_Xlo[mo] = hl;
            }
        }
        if (htid == 0){
            unsigned v;
            do {
                asm volatile("ld.acquire.gpu.global.u32 %0, [%1];"
                             : "=r"(v) : "l"(&cnt[s]) : "memory");
            } while (v < 64u);
        }
        asm volatile("bar.sync %0, 128;" :: "r"(barid) : "memory");
    }
}

// ------------------------ classifier ------------------------
__global__ void __launch_bounds__(256) k_cls(const float* __restrict__ cls_w,
                                             const float* __restrict__ cls_b, int parity){
    __shared__ float sW[L_][1024];
    __shared__ float sB[L_];
    int tid = threadIdx.x;
    for (int i = tid; i < L_*1024; i += 256) ((float*)sW)[i] = cls_w[i];
    if (tid < L_) sB[tid] = cls_b[tid];
    __syncthreads();
    int m = blockIdx.x*256 + tid;
    const float* xr = &g_xbuf[parity][(size_t)m*1024];
    float acc[L_];
    #pragma unroll
    for (int l=0;l<L_;l++) acc[l] = sB[l];
    for (int k = 0; k < 1024; k += 4){
        float4 xv = *(const float4*)&xr[k];
        #pragma unroll
        for (int l=0;l<L_;l++){
            float4 wv = *(const float4*)&sW[l][k];
            acc[l] += xv.x*wv.x + xv.y*wv.y + xv.z*wv.z + xv.w*wv.w;
        }
    }
    #pragma unroll
    for (int l=0;l<L_;l++) g_logits[m*L_ + l] = acc[l];
}

// ------------------------ CRF NLL (one block) ------------------------
__global__ void __launch_bounds__(128) k_crf(const int* __restrict__ att, const int* __restrict__ lab,
                                             const float* __restrict__ startv, const float* __restrict__ endv,
                                             const float* __restrict__ trans, float* __restrict__ out){
    __shared__ float sT[36], sS[6], sE[6];
    __shared__ float sAl[16][6];
    __shared__ float sNum[16], sLoss[16];
    int tid = threadIdx.x;
    if (tid < 36) sT[tid] = trans[tid];
    if (tid < 6){ sS[tid] = startv[tid]; sE[tid] = endv[tid]; }
    __syncthreads();

    bool isDen = tid < 96;
    bool isNum = (tid >= 96) && (tid < 112);
    int b = isDen ? tid/6 : tid-96;
    int j = tid % 6;

    float score = 0.f; int prev = 0;
    if (isDen) sAl[b][j] = sS[j] + g_logits[b*L_ + j];
    if (isNum){
        int l0 = lab[b*T_];
        int t0 = (l0 == -100) ? 0 : l0;
        score = sS[t0] + g_logits[b*L_ + t0];
        prev = t0;
    }
    __syncthreads();

    for (int t = 1; t < T_; ++t){
        float nxt = 0.f; bool mk = false;
        if (isDen){
            mk = (att[b*T_ + t] != 0) && (lab[b*T_ + t] != -100);
            float e = g_logits[(t*16 + b)*L_ + j];
            float mx = -1e30f;
            #pragma unroll
            for (int i2=0;i2<6;i2++) mx = fmaxf(mx, sAl[b][i2] + sT[i2*6+j]);
            float ss = 0.f;
            #pragma unroll
            for (int i2=0;i2<6;i2++) ss += expf(sAl[b][i2] + sT[i2*6+j] - mx);
            nxt = mx + logf(ss) + e;
        } else if (isNum){
            int lb = lab[b*T_ + t];
            bool m = (att[b*T_ + t] != 0) && (lb != -100);
            int tt = (lb == -100) ? 0 : lb;
            if (m){
                score += sT[prev*6 + tt] + g_logits[(t*16 + b)*L_ + tt];
                prev = tt;
            }
        }
        __syncthreads();
        if (isDen && mk) sAl[b][j] = nxt;
        __syncthreads();
    }

    if (isNum) sNum[b] = score + sE[prev];
    __syncthreads();
    if (tid < 16){
        float mx = -1e30f;
        #pragma unroll
        for (int jj=0;jj<6;jj++) mx = fmaxf(mx, sAl[tid][jj] + sE[jj]);
        float ss = 0.f;
        #pragma unroll
        for (int jj=0;jj<6;jj++) ss += expf(sAl[tid][jj] + sE[jj] - mx);
        float den = mx + logf(ss);
        sLoss[tid] = den - sNum[tid];
    }
    __syncthreads();
    if (tid == 0){
        float s = 0.f;
        for (int i=0;i<16;i++) s += sLoss[i];
        out[0] = s / 16.f;
    }
}

// ------------------------ launch ------------------------
extern "C" void kernel_launch(void* const* d_in, const int* in_sizes, int n_in,
                              void* d_out, int out_size){
    const float* emb    = (const float*)d_in[0];
    const int*   att    = (const int*)  d_in[1];
    const int*   lab    = (const int*)  d_in[2];
    const float* conv_w = (const float*)d_in[3];
    const float* conv_b = (const float*)d_in[4];
    const float* bn_g   = (const float*)d_in[5];
    const float* bn_b   = (const float*)d_in[6];
    const float* bn_m   = (const float*)d_in[7];
    const float* bn_v   = (const float*)d_in[8];
    const float* wih    = (const float*)d_in[9];
    const float* whh    = (const float*)d_in[10];
    const float* bih    = (const float*)d_in[11];
    const float* bhh    = (const float*)d_in[12];
    const float* cls_w  = (const float*)d_in[13];
    const float* cls_b  = (const float*)d_in[14];
    const float* crf_s  = (const float*)d_in[15];
    const float* crf_e  = (const float*)d_in[16];
    const float* crf_t  = (const float*)d_in[17];
    float* out = (float*)d_out;

    cudaFuncSetAttribute(k_recur3, cudaFuncAttributeMaxDynamicSharedMemorySize, R3_SMEM);
    cudaFuncSetAttribute(k_gate,   cudaFuncAttributeMaxDynamicSharedMemorySize, GT_SMEM);
    cudaFuncSetAttribute(k_convT,  cudaFuncAttributeMaxDynamicSharedMemorySize, GT_SMEM);

    k_cvt_e <<<B_*T_*E_/256, 256>>>(emb);
    k_cvt_cw<<<C_*KC_/256, 256>>>(conv_w);
    k_cvt_w <<<3*NG*KI/256, 256>>>(wih);
    k_pack_small<<<48, 256>>>(bih, bhh, bn_g, bn_b, bn_m, bn_v, conv_b);

    k_convT<<<dim3(C_/128, M_/128), 256, GT_SMEM>>>();

    for (int l = 0; l < 3; ++l){
        int outpar = (l + 1) & 1;
        int wF32    = (l == 2) ? 1 : 0;
        int wPlanes = (l == 2) ? 0 : 1;
        k_gate<<<dim3(NG/128, M_/128), 256, GT_SMEM>>>(l);
        k_reset<<<128, 256>>>();
        k_recur3<<<64, 256, R3_SMEM>>>(whh, l, outpar, wF32, wPlanes);
    }

    k_cls<<<M_/256, 256>>>(cls_w, cls_b, 1);
    k_crf<<<1, 128>>>(att, lab, crf_s, crf_e, crf_t, out);
}

// round 16
// speedup vs baseline: 1.0381x; 1.0381x over previous
#include <cuda_runtime.h>
#include <cuda_bf16.h>
#include <math.h>
#include <cstdint>

typedef unsigned long long ull;

#define T_ 1024
#define B_ 16
#define E_ 1024
#define H_ 512
#define C_ 1024
#define L_ 6
#define M_ (T_*B_)
#define NG 4096
#define KI 1024
#define KC_ (5*E_)              // 5120 conv GEMM K

// ------------------------ device scratch ------------------------
__device__ float g_xbuf[2][(size_t)M_*C_];       // fp32 activations (layer-3 out / classifier in)
__device__ float g_G[(size_t)M_*NG];             // input-projected gates [m][4096]
__device__ unsigned short g_Xhi[(size_t)M_*KI];  // bf16 hi plane of activations
__device__ unsigned short g_Xlo[(size_t)M_*KI];  // bf16 lo plane
__device__ unsigned short g_Whi[3][(size_t)NG*KI]; // bf16 hi of wih ([n][k] layout)
__device__ unsigned short g_Wlo[3][(size_t)NG*KI];
__device__ unsigned short g_Ehi[(size_t)B_*T_*E_]; // bf16 hi of embeddings
__device__ unsigned short g_Elo[(size_t)B_*T_*E_];
__device__ unsigned short g_CWhi[(size_t)C_*KC_];  // conv w planes, [c][dk*1024+e]
__device__ unsigned short g_CWlo[(size_t)C_*KC_];
__device__ float g_biasG[3][NG];
__device__ float g_bnA[C_], g_bnB[C_];
__device__ unsigned short g_hHi[2][2][H_*B_];    // h bf16 hi plane, [b*512+j]
__device__ unsigned short g_hLo[2][2][H_*B_];    // h bf16 lo plane
__device__ unsigned g_cnt[2][T_];
__device__ float g_logits[M_*L_];

// ------------------------ helpers ------------------------
__device__ __forceinline__ float sigf(float x){ return 1.f/(1.f + expf(-x)); }
__device__ __forceinline__ float sigf_fast(float x){ return __fdividef(1.f, 1.f + __expf(-x)); }
__device__ __forceinline__ float tanh_fast(float x){ return 1.f - __fdividef(2.f, __expf(2.f*x) + 1.f); }

__device__ __forceinline__ void split_bf(float v, unsigned short& h, unsigned short& l){
    __nv_bfloat16 hb = __float2bfloat16(v);
    h = __bfloat16_as_ushort(hb);
    l = __bfloat16_as_ushort(__float2bfloat16(v - __bfloat162float(hb)));
}

__device__ __forceinline__ unsigned smem_u32(const void* p){
    unsigned a; asm("{ .reg .u64 t; cvta.to.shared.u64 t, %1; cvt.u32.u64 %0, t; }" : "=r"(a) : "l"(p));
    return a;
}

#define LDSM4(r, a) \
    asm volatile("ldmatrix.sync.aligned.m8n8.x4.shared.b16 {%0,%1,%2,%3}, [%4];" \
        : "=r"((r)[0]),"=r"((r)[1]),"=r"((r)[2]),"=r"((r)[3]) : "r"(a))

#define LDSM2(r, a) \
    asm volatile("ldmatrix.sync.aligned.m8n8.x2.shared.b16 {%0,%1}, [%2];" \
        : "=r"((r)[0]),"=r"((r)[1]) : "r"(a))

#define MMA16816(dd, A, b0, b1) \
    asm volatile("mma.sync.aligned.m16n8k16.row.col.f32.bf16.bf16.f32 " \
        "{%0,%1,%2,%3}, {%4,%5,%6,%7}, {%8,%9}, {%0,%1,%2,%3};" \
        : "+f"((dd)[0]),"+f"((dd)[1]),"+f"((dd)[2]),"+f"((dd)[3]) \
        : "r"((A)[0]),"r"((A)[1]),"r"((A)[2]),"r"((A)[3]), "r"(b0),"r"(b1))

// ------------------------ pack / convert kernels ------------------------
__global__ void k_cvt_e(const float* __restrict__ emb){
    size_t idx = (size_t)blockIdx.x*256 + threadIdx.x;
    float v = emb[idx];
    unsigned short h, l; split_bf(v, h, l);
    g_Ehi[idx] = h;
    g_Elo[idx] = l;
}

__global__ void k_cvt_cw(const float* __restrict__ cw){
    size_t idx = (size_t)blockIdx.x*256 + threadIdx.x;
    int c  = (int)(idx / KC_);
    int kk = (int)(idx - (size_t)c*KC_);
    int dk = kk >> 10, e = kk & 1023;
    float v = cw[((size_t)c*E_ + e)*5 + dk];
    unsigned short h, l; split_bf(v, h, l);
    g_CWhi[idx] = h;
    g_CWlo[idx] = l;
}

__global__ void k_cvt_w(const float* __restrict__ wih){
    size_t idx = (size_t)blockIdx.x*256 + threadIdx.x;
    float v = wih[idx];
    unsigned short h, l; split_bf(v, h, l);
    ((unsigned short*)g_Whi)[idx] = h;
    ((unsigned short*)g_Wlo)[idx] = l;
}

__global__ void k_pack_small(const float* __restrict__ bih, const float* __restrict__ bhh,
                             const float* __restrict__ gamma, const float* __restrict__ beta,
                             const float* __restrict__ mean, const float* __restrict__ var,
                             const float* __restrict__ convb){
    int idx = blockIdx.x*256 + threadIdx.x;
    if (idx < 3*NG){
        int l = idx / NG; int n = idx - l*NG;
        int dir = n >> 11, r = n & 2047;
        int src = (l*2+dir)*2048 + r;
        ((float*)g_biasG)[idx] = bih[src] + bhh[src];
    }
    if (idx < C_){
        float s = gamma[idx] * rsqrtf(var[idx] + 1e-5f);
        g_bnA[idx] = s;
        g_bnB[idx] = s*convb[idx] + beta[idx] - mean[idx]*s;
    }
}

__global__ void k_reset(){
    int idx = blockIdx.x*256 + threadIdx.x;       // 128 blocks x 256 = 32768
    if (idx < 2*2*H_*B_){
        ((unsigned short*)g_hHi)[idx] = 0;
        ((unsigned short*)g_hLo)[idx] = 0;
    }
    if (idx < 2*T_) ((unsigned*)g_cnt)[idx] = 0u;
}

// ------------------------ shared HMMA tile layout ------------------------
#define PLANE_B 10240            // 128*80
#define STAGE_B (4*PLANE_B)      // 40960
#define GT_SMEM (2*STAGE_B)      // 81920

// ------------------------ split-bf16 HMMA conv GEMM + BN + ReLU ------------------------
__global__ void __launch_bounds__(256) k_convT(){
    extern __shared__ char smem[];
    unsigned sbase = smem_u32(smem);
    int tid = threadIdx.x;
    int wid = tid >> 5, lane = tid & 31;
    int m0 = blockIdx.y*128, n0 = blockIdx.x*128;

    auto prefetch = [&](int kc, int stg){
        unsigned sb = sbase + stg*STAGE_B;
        int dk = (kc*32) >> 10;
        int e_base = (kc*32) & 1023;
        #pragma unroll
        for (int it = 0; it < 8; ++it){
            int i = it*256 + tid;
            int p = i >> 9, rem = i & 511;
            int row = rem >> 2, c = rem & 3;
            unsigned sa = sb + p*PLANE_B + row*80 + c*16;
            if (p < 2){
                int m = m0 + row;
                int t = m >> 4, b = m & 15;
                int tp = t + dk - 2;
                const unsigned short* base = (p == 0) ? g_Ehi : g_Elo;
                const void* ga = base + ((size_t)b*1024 + tp)*1024 + e_base + c*8;
                unsigned sz = ((unsigned)tp < 1024u) ? 16u : 0u;
                asm volatile("cp.async.cg.shared.global [%0], [%1], 16, %2;"
                             :: "r"(sa), "l"(ga), "r"(sz) : "memory");
            } else {
                const unsigned short* base = (p == 2) ? g_CWhi : g_CWlo;
                const void* ga = base + (size_t)(n0 + row)*KC_ + kc*32 + c*8;
                asm volatile("cp.async.cg.shared.global [%0], [%1], 16;"
                             :: "r"(sa), "l"(ga) : "memory");
            }
        }
        asm volatile("cp.async.commit_group;" ::: "memory");
    };

    int wm = wid >> 1, wn = wid & 1;
    float d[2][8][4];
    #pragma unroll
    for (int mi=0;mi<2;++mi)
        #pragma unroll
        for (int ni=0;ni<8;++ni)
            #pragma unroll
            for (int q=0;q<4;++q) d[mi][ni][q] = 0.f;

    prefetch(0, 0);

    for (int kt = 0; kt < KC_/32; ++kt){
        int stg = kt & 1;
        asm volatile("cp.async.wait_group 0;" ::: "memory");
        __syncthreads();
        if (kt + 1 < KC_/32) prefetch(kt + 1, stg ^ 1);

        unsigned sb  = sbase + stg*STAGE_B;
        unsigned aHi = sb,            aLo = sb + PLANE_B;
        unsigned bHi = sb + 2*PLANE_B, bLo = sb + 3*PLANE_B;

        #pragma unroll
        for (int kh = 0; kh < 2; ++kh){
            unsigned Ah[2][4], Al[2][4];
            #pragma unroll
            for (int mi = 0; mi < 2; ++mi){
                int row = wm*32 + mi*16 + (lane & 15);
                int ch  = kh*2 + (lane >> 4);
                unsigned off = row*80 + ch*16;
                LDSM4(Ah[mi], aHi + off);
                LDSM4(Al[mi], aLo + off);
            }
            unsigned Bh[4][4], Bl[4][4];
            #pragma unroll
            for (int pr = 0; pr < 4; ++pr){
                int row = wn*64 + pr*16 + (lane & 7) + ((lane >> 4) << 3);
                int ch  = kh*2 + ((lane >> 3) & 1);
                unsigned off = row*80 + ch*16;
                LDSM4(Bh[pr], bHi + off);
                LDSM4(Bl[pr], bLo + off);
            }
            #pragma unroll
            for (int mi = 0; mi < 2; ++mi){
                #pragma unroll
                for (int pr = 0; pr < 4; ++pr){
                    MMA16816(d[mi][2*pr],   Ah[mi], Bh[pr][0], Bh[pr][1]);
                    MMA16816(d[mi][2*pr],   Ah[mi], Bl[pr][0], Bl[pr][1]);
                    MMA16816(d[mi][2*pr],   Al[mi], Bh[pr][0], Bh[pr][1]);
                    MMA16816(d[mi][2*pr+1], Ah[mi], Bh[pr][2], Bh[pr][3]);
                    MMA16816(d[mi][2*pr+1], Ah[mi], Bl[pr][2], Bl[pr][3]);
                    MMA16816(d[mi][2*pr+1], Al[mi], Bh[pr][2], Bh[pr][3]);
                }
            }
        }
    }

    int qr = lane >> 2, qc = lane & 3;
    #pragma unroll
    for (int mi = 0; mi < 2; ++mi){
        #pragma unroll
        for (int ni = 0; ni < 8; ++ni){
            int col = n0 + wn*64 + ni*8 + qc*2;
            float2 A = *(const float2*)&g_bnA[col];
            float2 Bb = *(const float2*)&g_bnB[col];
            int r0 = m0 + wm*32 + mi*16 + qr;
            float v00 = fmaxf(d[mi][ni][0]*A.x + Bb.x, 0.f);
            float v01 = fmaxf(d[mi][ni][1]*A.y + Bb.y, 0.f);
            float v10 = fmaxf(d[mi][ni][2]*A.x + Bb.x, 0.f);
            float v11 = fmaxf(d[mi][ni][3]*A.y + Bb.y, 0.f);
            ushort2 h0, l0, h1, l1;
            split_bf(v00, h0.x, l0.x); split_bf(v01, h0.y, l0.y);
            split_bf(v10, h1.x, l1.x); split_bf(v11, h1.y, l1.y);
            *(ushort2*)&g_Xhi[(size_t)r0*1024 + col]     = h0;
            *(ushort2*)&g_Xlo[(size_t)r0*1024 + col]     = l0;
            *(ushort2*)&g_Xhi[(size_t)(r0+8)*1024 + col] = h1;
            *(ushort2*)&g_Xlo[(size_t)(r0+8)*1024 + col] = l1;
        }
    }
}

// ------------------------ mma.sync split-bf16 gate GEMM ------------------------
__global__ void __launch_bounds__(256) k_gate(int layer){
    extern __shared__ char smem[];
    unsigned sbase = smem_u32(smem);
    int tid = threadIdx.x;
    int wid = tid >> 5, lane = tid & 31;
    int m0 = blockIdx.y*128, n0 = blockIdx.x*128;

    const unsigned short* srcs[4] = {
        g_Xhi + (size_t)m0*1024,
        g_Xlo + (size_t)m0*1024,
        g_Whi[layer] + (size_t)n0*1024,
        g_Wlo[layer] + (size_t)n0*1024
    };

    auto prefetch = [&](int kc, int stg){
        unsigned sb = sbase + stg*STAGE_B;
        #pragma unroll
        for (int it = 0; it < 8; ++it){
            int i = it*256 + tid;
            int p = i >> 9, rem = i & 511;
            int row = rem >> 2, c = rem & 3;
            unsigned sa = sb + p*PLANE_B + row*80 + c*16;
            const void* ga = srcs[p] + (size_t)row*1024 + kc*32 + c*8;
            asm volatile("cp.async.cg.shared.global [%0], [%1], 16;" :: "r"(sa), "l"(ga) : "memory");
        }
        asm volatile("cp.async.commit_group;" ::: "memory");
    };

    int wm = wid >> 1, wn = wid & 1;
    float d[2][8][4];
    #pragma unroll
    for (int mi=0;mi<2;++mi)
        #pragma unroll
        for (int ni=0;ni<8;++ni)
            #pragma unroll
            for (int q=0;q<4;++q) d[mi][ni][q] = 0.f;

    prefetch(0, 0);

    for (int kt = 0; kt < 32; ++kt){
        int stg = kt & 1;
        asm volatile("cp.async.wait_group 0;" ::: "memory");
        __syncthreads();
        if (kt + 1 < 32) prefetch(kt + 1, stg ^ 1);

        unsigned sb  = sbase + stg*STAGE_B;
        unsigned aHi = sb,            aLo = sb + PLANE_B;
        unsigned bHi = sb + 2*PLANE_B, bLo = sb + 3*PLANE_B;

        #pragma unroll
        for (int kh = 0; kh < 2; ++kh){
            unsigned Ah[2][4], Al[2][4];
            #pragma unroll
            for (int mi = 0; mi < 2; ++mi){
                int row = wm*32 + mi*16 + (lane & 15);
                int ch  = kh*2 + (lane >> 4);
                unsigned off = row*80 + ch*16;
                LDSM4(Ah[mi], aHi + off);
                LDSM4(Al[mi], aLo + off);
            }
            unsigned Bh[4][4], Bl[4][4];
            #pragma unroll
            for (int pr = 0; pr < 4; ++pr){
                int row = wn*64 + pr*16 + (lane & 7) + ((lane >> 4) << 3);
                int ch  = kh*2 + ((lane >> 3) & 1);
                unsigned off = row*80 + ch*16;
                LDSM4(Bh[pr], bHi + off);
                LDSM4(Bl[pr], bLo + off);
            }
            #pragma unroll
            for (int mi = 0; mi < 2; ++mi){
                #pragma unroll
                for (int pr = 0; pr < 4; ++pr){
                    MMA16816(d[mi][2*pr],   Ah[mi], Bh[pr][0], Bh[pr][1]);
                    MMA16816(d[mi][2*pr],   Ah[mi], Bl[pr][0], Bl[pr][1]);
                    MMA16816(d[mi][2*pr],   Al[mi], Bh[pr][0], Bh[pr][1]);
                    MMA16816(d[mi][2*pr+1], Ah[mi], Bh[pr][2], Bh[pr][3]);
                    MMA16816(d[mi][2*pr+1], Ah[mi], Bl[pr][2], Bl[pr][3]);
                    MMA16816(d[mi][2*pr+1], Al[mi], Bh[pr][2], Bh[pr][3]);
                }
            }
        }
    }

    int qr = lane >> 2, qc = lane & 3;
    #pragma unroll
    for (int mi = 0; mi < 2; ++mi){
        #pragma unroll
        for (int ni = 0; ni < 8; ++ni){
            int col = n0 + wn*64 + ni*8 + qc*2;
            float2 bq = *(const float2*)&g_biasG[layer][col];
            int r0 = m0 + wm*32 + mi*16 + qr;
            float2 v0 = make_float2(d[mi][ni][0] + bq.x, d[mi][ni][1] + bq.y);
            *(float2*)&g_G[(size_t)r0*NG + col] = v0;
            float2 v1 = make_float2(d[mi][ni][2] + bq.x, d[mi][ni][3] + bq.y);
            *(float2*)&g_G[(size_t)(r0+8)*NG + col] = v1;
        }
    }
}

// ------------------------ persistent BiLSTM recurrence v3b ------------------------
// Same as R15 (full K=512, correct) but with per-term accumulators: the three
// split-bf16 terms (HH, HL, LH) accumulate into independent registers, giving
// 3 parallel MMA dependency chains instead of one 96-deep serial chain.
#define R3_PH(h)   ((h)*33280)
#define R3_SMEM    66560

__global__ void __launch_bounds__(256) k_recur3(const float* __restrict__ whh, int layer, int outparity,
                                                int writeF32, int writePlanes){
    extern __shared__ char smem[];
    unsigned sb = smem_u32(smem);
    int tid = threadIdx.x;
    int half = tid >> 7;                 // 0 = fw, 1 = bw
    int htid = tid & 127;
    int hwid = htid >> 5;                // warp within half, 0..3
    int lane = tid & 31;
    int dir = half;
    int bid = blockIdx.x;
    int j0 = bid*8;

    unsigned phBase = sb + R3_PH(half);  // in-loop: hi plane = phBase, lo = phBase + 16640

    // ---- stage Whh HI (gate-interleaved rows, 32 rows x 1040B flat) ----
    for (int i = htid; i < 4096; i += 128){     // 32 rows x 128 float4
        int row = i >> 7;
        int k4  = (i & 127) * 4;
        int w_ = row >> 3, r_ = row & 7;
        int g = r_ >> 1, jp = r_ & 1;
        float4 w = *(const float4*)&whh[(((size_t)(layer*2+dir))*2048 + g*512 + j0 + 2*w_ + jp)*512 + k4];
        unsigned short h0,l0,h1,l1,h2,l2,h3,l3;
        split_bf(w.x,h0,l0); split_bf(w.y,h1,l1); split_bf(w.z,h2,l2); split_bf(w.w,h3,l3);
        *(uint2*)(smem + R3_PH(half) + row*1040 + k4*2) =
            make_uint2((unsigned)h0 | ((unsigned)h1<<16), (unsigned)h2 | ((unsigned)h3<<16));
    }
    __syncthreads();
    unsigned Bh[32][2], Bl[32][2];
    {
        int rowB = hwid*8 + (lane & 7);
        int chB  = (lane >> 3) & 1;
        #pragma unroll
        for (int kt = 0; kt < 32; ++kt){
            unsigned off = rowB*1040 + kt*32 + chB*16;
            LDSM2(Bh[kt], phBase + off);
        }
    }
    __syncthreads();
    // ---- stage Whh LO (reuse region) ----
    for (int i = htid; i < 4096; i += 128){
        int row = i >> 7;
        int k4  = (i & 127) * 4;
        int w_ = row >> 3, r_ = row & 7;
        int g = r_ >> 1, jp = r_ & 1;
        float4 w = *(const float4*)&whh[(((size_t)(layer*2+dir))*2048 + g*512 + j0 + 2*w_ + jp)*512 + k4];
        unsigned short h0,l0,h1,l1,h2,l2,h3,l3;
        split_bf(w.x,h0,l0); split_bf(w.y,h1,l1); split_bf(w.z,h2,l2); split_bf(w.w,h3,l3);
        *(uint2*)(smem + R3_PH(half) + row*1040 + k4*2) =
            make_uint2((unsigned)l0 | ((unsigned)l1<<16), (unsigned)l2 | ((unsigned)l3<<16));
    }
    __syncthreads();
    {
        int rowB = hwid*8 + (lane & 7);
        int chB  = (lane >> 3) & 1;
        #pragma unroll
        for (int kt = 0; kt < 32; ++kt){
            unsigned off = rowB*1040 + kt*32 + chB*16;
            LDSM2(Bl[kt], phBase + off);
        }
    }
    __syncthreads();

    // ---- per-lane cell identity ----
    int qr = lane >> 2, qc = lane & 3;
    int bcell = qr + ((qc >> 1) << 3);          // batch 0..15
    int jpar = qc & 1;
    int jloc = j0 + 2*hwid + jpar;              // j within [0,512)
    int colG = dir*2048 + jloc;                 // + g*512 per gate
    float cReg = 0.f;
    float gReg[4];
    {
        int t0 = dir ? (T_-1) : 0;
        #pragma unroll
        for (int g2 = 0; g2 < 4; ++g2)
            gReg[g2] = g_G[(size_t)(t0*16 + bcell)*NG + colG + g2*512];
    }

    float* xout = g_xbuf[outparity];
    unsigned* cnt = &g_cnt[dir][0];
    int offA_row = (lane & 15)*1040 + (lane >> 4)*16;
    int barid = 1 + half;

    for (int s = 0; s < T_; ++s){
        // ---- stage h planes via cp.async (global -> smem, no unpack) ----
        const char* srcHi = (const char*)&g_hHi[dir][s & 1][0];
        const char* srcLo = (const char*)&g_hLo[dir][s & 1][0];
        #pragma unroll
        for (int it = 0; it < 16; ++it){
            int i = it*128 + htid;               // 0..2047 16B chunks
            int p = i >> 10;                     // 0 = hi, 1 = lo
            int rem = i & 1023;
            int b = rem >> 6, off = (rem & 63)*16;
            unsigned sa = phBase + p*16640 + b*1040 + off;
            const char* ga = (p ? srcLo : srcHi) + b*1024 + off;
            asm volatile("cp.async.cg.shared.global [%0], [%1], 16;" :: "r"(sa), "l"(ga) : "memory");
        }
        asm volatile("cp.async.commit_group;" ::: "memory");
        asm volatile("cp.async.wait_group 0;" ::: "memory");
        asm volatile("bar.sync %0, 128;" :: "r"(barid) : "memory");

        // ---- MMA: full K=512, 3 independent accumulator chains (HH, HL, LH) ----
        float dHH[4] = {0.f,0.f,0.f,0.f};
        float dHL[4] = {0.f,0.f,0.f,0.f};
        float dLH[4] = {0.f,0.f,0.f,0.f};
        #pragma unroll
        for (int kt = 0; kt < 32; ++kt){
            unsigned offA = offA_row + kt*32;
            unsigned Ah[4], Al[4];
            LDSM4(Ah, phBase + offA);
            LDSM4(Al, phBase + 16640 + offA);
            MMA16816(dHH, Ah, Bh[kt][0], Bh[kt][1]);
            MMA16816(dHL, Ah, Bl[kt][0], Bl[kt][1]);
            MMA16816(dLH, Al, Bh[kt][0], Bh[kt][1]);
        }
        float d[4];
        #pragma unroll
        for (int q = 0; q < 4; ++q) d[q] = dHH[q] + dHL[q] + dLH[q];

        // ---- 4x4 lane-quad xor transpose: gate[g] for this lane's cell ----
        float gate[4];
        gate[qc] = d[qc];
        #pragma unroll
        for (int m = 1; m < 4; ++m){
            int sel = qc ^ m;
            float pub = (sel == 0) ? d[0] : (sel == 1) ? d[1] : (sel == 2) ? d[2] : d[3];
            float got = __shfl_xor_sync(0xffffffffu, pub, m);
            gate[sel] = got;
        }

        // ---- prefetch next-step G ----
        float ng[4] = {0.f,0.f,0.f,0.f};
        if (s+1 < T_){
            int tn = dir ? (T_-2 - s) : (s+1);
            #pragma unroll
            for (int g2 = 0; g2 < 4; ++g2)
                ng[g2] = g_G[(size_t)(tn*16 + bcell)*NG + colG + g2*512];
        }

        // ---- cell update (registers only) ----
        float a0 = gReg[0] + gate[0];
        float a1 = gReg[1] + gate[1];
        float a2 = gReg[2] + gate[2];
        float a3 = gReg[3] + gate[3];
        cReg = sigf_fast(a1)*cReg + sigf_fast(a0)*tanh_fast(a2);
        float hval = sigf_fast(a3)*tanh_fast(cReg);
        unsigned short hh, hl;
        split_bf(hval, hh, hl);
        g_hHi[dir][(s+1)&1][bcell*512 + jloc] = hh;
        g_hLo[dir][(s+1)&1][bcell*512 + jloc] = hl;
        gReg[0] = ng[0]; gReg[1] = ng[1]; gReg[2] = ng[2]; gReg[3] = ng[3];

        asm volatile("bar.sync %0, 128;" :: "r"(barid) : "memory");
        if (htid == 0){
            asm volatile("red.release.gpu.global.add.u32 [%0], %1;"
                         :: "l"(&cnt[s]), "r"(1u) : "memory");
        }
        // deferred next-layer output stores (off the release chain)
        {
            int t2 = dir ? (T_-1 - s) : s;
            size_t mo = (size_t)(t2*16 + bcell)*1024 + dir*512 + jloc;
            if (writeF32) xout[mo] = hval;
            if (writePlanes){
                g_Xhi[mo] = hh;
                g_Xlo[mo] = hl;
            }
        }
        if (htid == 0){
            unsigned v;
            do {
                asm volatile("ld.acquire.gpu.global.u32 %0, [%1];"
                             : "=r"(v) : "l"(&cnt[s]) : "memory");
            } while (v < 64u);
        }
        asm volatile("bar.sync %0, 128;" :: "r"(barid) : "memory");
    }
}

// ------------------------ classifier ------------------------
__global__ void __launch_bounds__(256) k_cls(const float* __restrict__ cls_w,
                                             const float* __restrict__ cls_b, int parity){
    __shared__ float sW[L_][1024];
    __shared__ float sB[L_];
    int tid = threadIdx.x;
    for (int i = tid; i < L_*1024; i += 256) ((float*)sW)[i] = cls_w[i];
    if (tid < L_) sB[tid] = cls_b[tid];
    __syncthreads();
    int m = blockIdx.x*256 + tid;
    const float* xr = &g_xbuf[parity][(size_t)m*1024];
    float acc[L_];
    #pragma unroll
    for (int l=0;l<L_;l++) acc[l] = sB[l];
    for (int k = 0; k < 1024; k += 4){
        float4 xv = *(const float4*)&xr[k];
        #pragma unroll
        for (int l=0;l<L_;l++){
            float4 wv = *(const float4*)&sW[l][k];
            acc[l] += xv.x*wv.x + xv.y*wv.y + xv.z*wv.z + xv.w*wv.w;
        }
    }
    #pragma unroll
    for (int l=0;l<L_;l++) g_logits[m*L_ + l] = acc[l];
}

// ------------------------ CRF NLL (one block) ------------------------
__global__ void __launch_bounds__(128) k_crf(const int* __restrict__ att, const int* __restrict__ lab,
                                             const float* __restrict__ startv, const float* __restrict__ endv,
                                             const float* __restrict__ trans, float* __restrict__ out){
    __shared__ float sT[36], sS[6], sE[6];
    __shared__ float sAl[16][6];
    __shared__ float sNum[16], sLoss[16];
    int tid = threadIdx.x;
    if (tid < 36) sT[tid] = trans[tid];
    if (tid < 6){ sS[tid] = startv[tid]; sE[tid] = endv[tid]; }
    __syncthreads();

    bool isDen = tid < 96;
    bool isNum = (tid >= 96) && (tid < 112);
    int b = isDen ? tid/6 : tid-96;
    int j = tid % 6;

    float score = 0.f; int prev = 0;
    if (isDen) sAl[b][j] = sS[j] + g_logits[b*L_ + j];
    if (isNum){
        int l0 = lab[b*T_];
        int t0 = (l0 == -100) ? 0 : l0;
        score = sS[t0] + g_logits[b*L_ + t0];
        prev = t0;
    }
    __syncthreads();

    for (int t = 1; t < T_; ++t){
        float nxt = 0.f; bool mk = false;
        if (isDen){
            mk = (att[b*T_ + t] != 0) && (lab[b*T_ + t] != -100);
            float e = g_logits[(t*16 + b)*L_ + j];
            float mx = -1e30f;
            #pragma unroll
            for (int i2=0;i2<6;i2++) mx = fmaxf(mx, sAl[b][i2] + sT[i2*6+j]);
            float ss = 0.f;
            #pragma unroll
            for (int i2=0;i2<6;i2++) ss += expf(sAl[b][i2] + sT[i2*6+j] - mx);
            nxt = mx + logf(ss) + e;
        } else if (isNum){
            int lb = lab[b*T_ + t];
            bool m = (att[b*T_ + t] != 0) && (lb != -100);
            int tt = (lb == -100) ? 0 : lb;
            if (m){
                score += sT[prev*6 + tt] + g_logits[(t*16 + b)*L_ + tt];
                prev = tt;
            }
        }
        __syncthreads();
        if (isDen && mk) sAl[b][j] = nxt;
        __syncthreads();
    }

    if (isNum) sNum[b] = score + sE[prev];
    __syncthreads();
    if (tid < 16){
        float mx = -1e30f;
        #pragma unroll
        for (int jj=0;jj<6;jj++) mx = fmaxf(mx, sAl[tid][jj] + sE[jj]);
        float ss = 0.f;
        #pragma unroll
        for (int jj=0;jj<6;jj++) ss += expf(sAl[tid][jj] + sE[jj] - mx);
        float den = mx + logf(ss);
        sLoss[tid] = den - sNum[tid];
    }
    __syncthreads();
    if (tid == 0){
        float s = 0.f;
        for (int i=0;i<16;i++) s += sLoss[i];
        out[0] = s / 16.f;
    }
}

// ------------------------ launch ------------------------
extern "C" void kernel_launch(void* const* d_in, const int* in_sizes, int n_in,
                              void* d_out, int out_size){
    const float* emb    = (const float*)d_in[0];
    const int*   att    = (const int*)  d_in[1];
    const int*   lab    = (const int*)  d_in[2];
    const float* conv_w = (const float*)d_in[3];
    const float* conv_b = (const float*)d_in[4];
    const float* bn_g   = (const float*)d_in[5];
    const float* bn_b   = (const float*)d_in[6];
    const float* bn_m   = (const float*)d_in[7];
    const float* bn_v   = (const float*)d_in[8];
    const float* wih    = (const float*)d_in[9];
    const float* whh    = (const float*)d_in[10];
    const float* bih    = (const float*)d_in[11];
    const float* bhh    = (const float*)d_in[12];
    const float* cls_w  = (const float*)d_in[13];
    const float* cls_b  = (const float*)d_in[14];
    const float* crf_s  = (const float*)d_in[15];
    const float* crf_e  = (const float*)d_in[16];
    const float* crf_t  = (const float*)d_in[17];
    float* out = (float*)d_out;

    cudaFuncSetAttribute(k_recur3, cudaFuncAttributeMaxDynamicSharedMemorySize, R3_SMEM);
    cudaFuncSetAttribute(k_gate,   cudaFuncAttributeMaxDynamicSharedMemorySize, GT_SMEM);
    cudaFuncSetAttribute(k_convT,  cudaFuncAttributeMaxDynamicSharedMemorySize, GT_SMEM);

    k_cvt_e <<<B_*T_*E_/256, 256>>>(emb);
    k_cvt_cw<<<C_*KC_/256, 256>>>(conv_w);
    k_cvt_w <<<3*NG*KI/256, 256>>>(wih);
    k_pack_small<<<48, 256>>>(bih, bhh, bn_g, bn_b, bn_m, bn_v, conv_b);

    k_convT<<<dim3(C_/128, M_/128), 256, GT_SMEM>>>();

    for (int l = 0; l < 3; ++l){
        int outpar = (l + 1) & 1;
        int wF32    = (l == 2) ? 1 : 0;
        int wPlanes = (l == 2) ? 0 : 1;
        k_gate<<<dim3(NG/128, M_/128), 256, GT_SMEM>>>(l);
        k_reset<<<128, 256>>>();
        k_recur3<<<64, 256, R3_SMEM>>>(whh, l, outpar, wF32, wPlanes);
    }

    k_cls<<<M_/256, 256>>>(cls_w, cls_b, 1);
    k_crf<<<1, 128>>>(att, lab, crf_s, crf_e, crf_t, out);
}

// round 17
// speedup vs baseline: 1.1097x; 1.0690x over previous
#include <cuda_runtime.h>
#include <cuda_bf16.h>
#include <math.h>
#include <cstdint>

typedef unsigned long long ull;

#define T_ 1024
#define B_ 16
#define E_ 1024
#define H_ 512
#define C_ 1024
#define L_ 6
#define M_ (T_*B_)
#define NG 4096
#define KI 1024
#define KC_ (5*E_)              // 5120 conv GEMM K

// ------------------------ device scratch ------------------------
__device__ float g_xbuf[2][(size_t)M_*C_];       // fp32 activations (layer-3 out / classifier in)
__device__ float g_G[(size_t)M_*NG];             // input-projected gates [m][4096]
__device__ unsigned short g_Xhi[(size_t)M_*KI];  // bf16 hi plane of activations
__device__ unsigned short g_Xlo[(size_t)M_*KI];  // bf16 lo plane
__device__ unsigned short g_Whi[3][(size_t)NG*KI]; // bf16 hi of wih ([n][k] layout)
__device__ unsigned short g_Wlo[3][(size_t)NG*KI];
__device__ unsigned short g_Ehi[(size_t)B_*T_*E_]; // bf16 hi of embeddings
__device__ unsigned short g_Elo[(size_t)B_*T_*E_];
__device__ unsigned short g_CWhi[(size_t)C_*KC_];  // conv w planes, [c][dk*1024+e]
__device__ unsigned short g_CWlo[(size_t)C_*KC_];
__device__ float g_biasG[3][NG];
__device__ float g_bnA[C_], g_bnB[C_];
__device__ unsigned g_hPk[2][2][H_*B_];          // packed h: (bf16hi<<16)|bf16lo, [b*512+j]
__device__ unsigned g_cnt[2][T_];
__device__ float g_logits[M_*L_];

// ------------------------ helpers ------------------------
__device__ __forceinline__ float sigf(float x){ return 1.f/(1.f + expf(-x)); }
__device__ __forceinline__ float sigf_fast(float x){ return __fdividef(1.f, 1.f + __expf(-x)); }
__device__ __forceinline__ float tanh_fast(float x){ return 1.f - __fdividef(2.f, __expf(2.f*x) + 1.f); }

__device__ __forceinline__ void split_bf(float v, unsigned short& h, unsigned short& l){
    __nv_bfloat16 hb = __float2bfloat16(v);
    h = __bfloat16_as_ushort(hb);
    l = __bfloat16_as_ushort(__float2bfloat16(v - __bfloat162float(hb)));
}

__device__ __forceinline__ unsigned smem_u32(const void* p){
    unsigned a; asm("{ .reg .u64 t; cvta.to.shared.u64 t, %1; cvt.u32.u64 %0, t; }" : "=r"(a) : "l"(p));
    return a;
}

#define LDSM4(r, a) \
    asm volatile("ldmatrix.sync.aligned.m8n8.x4.shared.b16 {%0,%1,%2,%3}, [%4];" \
        : "=r"((r)[0]),"=r"((r)[1]),"=r"((r)[2]),"=r"((r)[3]) : "r"(a))

#define MMA16816(dd, A, b0, b1) \
    asm volatile("mma.sync.aligned.m16n8k16.row.col.f32.bf16.bf16.f32 " \
        "{%0,%1,%2,%3}, {%4,%5,%6,%7}, {%8,%9}, {%0,%1,%2,%3};" \
        : "+f"((dd)[0]),"+f"((dd)[1]),"+f"((dd)[2]),"+f"((dd)[3]) \
        : "r"((A)[0]),"r"((A)[1]),"r"((A)[2]),"r"((A)[3]), "r"(b0),"r"(b1))

// ------------------------ pack / convert kernels ------------------------
__global__ void k_cvt_e(const float* __restrict__ emb){
    size_t idx = (size_t)blockIdx.x*256 + threadIdx.x;
    float v = emb[idx];
    unsigned short h, l; split_bf(v, h, l);
    g_Ehi[idx] = h;
    g_Elo[idx] = l;
}

__global__ void k_cvt_cw(const float* __restrict__ cw){
    size_t idx = (size_t)blockIdx.x*256 + threadIdx.x;
    int c  = (int)(idx / KC_);
    int kk = (int)(idx - (size_t)c*KC_);
    int dk = kk >> 10, e = kk & 1023;
    float v = cw[((size_t)c*E_ + e)*5 + dk];
    unsigned short h, l; split_bf(v, h, l);
    g_CWhi[idx] = h;
    g_CWlo[idx] = l;
}

__global__ void k_cvt_w(const float* __restrict__ wih){
    size_t idx = (size_t)blockIdx.x*256 + threadIdx.x;
    float v = wih[idx];
    unsigned short h, l; split_bf(v, h, l);
    ((unsigned short*)g_Whi)[idx] = h;
    ((unsigned short*)g_Wlo)[idx] = l;
}

__global__ void k_pack_small(const float* __restrict__ bih, const float* __restrict__ bhh,
                             const float* __restrict__ gamma, const float* __restrict__ beta,
                             const float* __restrict__ mean, const float* __restrict__ var,
                             const float* __restrict__ convb){
    int idx = blockIdx.x*256 + threadIdx.x;
    if (idx < 3*NG){
        int l = idx / NG; int n = idx - l*NG;
        int dir = n >> 11, r = n & 2047;
        int src = (l*2+dir)*2048 + r;
        ((float*)g_biasG)[idx] = bih[src] + bhh[src];
    }
    if (idx < C_){
        float s = gamma[idx] * rsqrtf(var[idx] + 1e-5f);
        g_bnA[idx] = s;
        g_bnB[idx] = s*convb[idx] + beta[idx] - mean[idx]*s;
    }
}

__global__ void k_reset(){
    int idx = blockIdx.x*256 + threadIdx.x;
    if (idx < 2*2*H_*B_) ((unsigned*)g_hPk)[idx] = 0u;
    if (idx < 2*T_) ((unsigned*)g_cnt)[idx] = 0u;
}

// ------------------------ shared HMMA tile layout ------------------------
#define PLANE_B 10240            // 128*80
#define STAGE_B (4*PLANE_B)      // 40960
#define GT_SMEM (2*STAGE_B)      // 81920

// ------------------------ split-bf16 HMMA conv GEMM + BN + ReLU ------------------------
__global__ void __launch_bounds__(256) k_convT(){
    extern __shared__ char smem[];
    unsigned sbase = smem_u32(smem);
    int tid = threadIdx.x;
    int wid = tid >> 5, lane = tid & 31;
    int m0 = blockIdx.y*128, n0 = blockIdx.x*128;

    auto prefetch = [&](int kc, int stg){
        unsigned sb = sbase + stg*STAGE_B;
        int dk = (kc*32) >> 10;
        int e_base = (kc*32) & 1023;
        #pragma unroll
        for (int it = 0; it < 8; ++it){
            int i = it*256 + tid;
            int p = i >> 9, rem = i & 511;
            int row = rem >> 2, c = rem & 3;
            unsigned sa = sb + p*PLANE_B + row*80 + c*16;
            if (p < 2){
                int m = m0 + row;
                int t = m >> 4, b = m & 15;
                int tp = t + dk - 2;
                const unsigned short* base = (p == 0) ? g_Ehi : g_Elo;
                const void* ga = base + ((size_t)b*1024 + tp)*1024 + e_base + c*8;
                unsigned sz = ((unsigned)tp < 1024u) ? 16u : 0u;
                asm volatile("cp.async.cg.shared.global [%0], [%1], 16, %2;"
                             :: "r"(sa), "l"(ga), "r"(sz) : "memory");
            } else {
                const unsigned short* base = (p == 2) ? g_CWhi : g_CWlo;
                const void* ga = base + (size_t)(n0 + row)*KC_ + kc*32 + c*8;
                asm volatile("cp.async.cg.shared.global [%0], [%1], 16;"
                             :: "r"(sa), "l"(ga) : "memory");
            }
        }
        asm volatile("cp.async.commit_group;" ::: "memory");
    };

    int wm = wid >> 1, wn = wid & 1;
    float d[2][8][4];
    #pragma unroll
    for (int mi=0;mi<2;++mi)
        #pragma unroll
        for (int ni=0;ni<8;++ni)
            #pragma unroll
            for (int q=0;q<4;++q) d[mi][ni][q] = 0.f;

    prefetch(0, 0);

    for (int kt = 0; kt < KC_/32; ++kt){
        int stg = kt & 1;
        asm volatile("cp.async.wait_group 0;" ::: "memory");
        __syncthreads();
        if (kt + 1 < KC_/32) prefetch(kt + 1, stg ^ 1);

        unsigned sb  = sbase + stg*STAGE_B;
        unsigned aHi = sb,            aLo = sb + PLANE_B;
        unsigned bHi = sb + 2*PLANE_B, bLo = sb + 3*PLANE_B;

        #pragma unroll
        for (int kh = 0; kh < 2; ++kh){
            unsigned Ah[2][4], Al[2][4];
            #pragma unroll
            for (int mi = 0; mi < 2; ++mi){
                int row = wm*32 + mi*16 + (lane & 15);
                int ch  = kh*2 + (lane >> 4);
                unsigned off = row*80 + ch*16;
                LDSM4(Ah[mi], aHi + off);
                LDSM4(Al[mi], aLo + off);
            }
            unsigned Bh[4][4], Bl[4][4];
            #pragma unroll
            for (int pr = 0; pr < 4; ++pr){
                int row = wn*64 + pr*16 + (lane & 7) + ((lane >> 4) << 3);
                int ch  = kh*2 + ((lane >> 3) & 1);
                unsigned off = row*80 + ch*16;
                LDSM4(Bh[pr], bHi + off);
                LDSM4(Bl[pr], bLo + off);
            }
            #pragma unroll
            for (int mi = 0; mi < 2; ++mi){
                #pragma unroll
                for (int pr = 0; pr < 4; ++pr){
                    MMA16816(d[mi][2*pr],   Ah[mi], Bh[pr][0], Bh[pr][1]);
                    MMA16816(d[mi][2*pr],   Ah[mi], Bl[pr][0], Bl[pr][1]);
                    MMA16816(d[mi][2*pr],   Al[mi], Bh[pr][0], Bh[pr][1]);
                    MMA16816(d[mi][2*pr+1], Ah[mi], Bh[pr][2], Bh[pr][3]);
                    MMA16816(d[mi][2*pr+1], Ah[mi], Bl[pr][2], Bl[pr][3]);
                    MMA16816(d[mi][2*pr+1], Al[mi], Bh[pr][2], Bh[pr][3]);
                }
            }
        }
    }

    int qr = lane >> 2, qc = lane & 3;
    #pragma unroll
    for (int mi = 0; mi < 2; ++mi){
        #pragma unroll
        for (int ni = 0; ni < 8; ++ni){
            int col = n0 + wn*64 + ni*8 + qc*2;
            float2 A = *(const float2*)&g_bnA[col];
            float2 Bb = *(const float2*)&g_bnB[col];
            int r0 = m0 + wm*32 + mi*16 + qr;
            float v00 = fmaxf(d[mi][ni][0]*A.x + Bb.x, 0.f);
            float v01 = fmaxf(d[mi][ni][1]*A.y + Bb.y, 0.f);
            float v10 = fmaxf(d[mi][ni][2]*A.x + Bb.x, 0.f);
            float v11 = fmaxf(d[mi][ni][3]*A.y + Bb.y, 0.f);
            ushort2 h0, l0, h1, l1;
            split_bf(v00, h0.x, l0.x); split_bf(v01, h0.y, l0.y);
            split_bf(v10, h1.x, l1.x); split_bf(v11, h1.y, l1.y);
            *(ushort2*)&g_Xhi[(size_t)r0*1024 + col]     = h0;
            *(ushort2*)&g_Xlo[(size_t)r0*1024 + col]     = l0;
            *(ushort2*)&g_Xhi[(size_t)(r0+8)*1024 + col] = h1;
            *(ushort2*)&g_Xlo[(size_t)(r0+8)*1024 + col] = l1;
        }
    }
}

// ------------------------ mma.sync split-bf16 gate GEMM ------------------------
__global__ void __launch_bounds__(256) k_gate(int layer){
    extern __shared__ char smem[];
    unsigned sbase = smem_u32(smem);
    int tid = threadIdx.x;
    int wid = tid >> 5, lane = tid & 31;
    int m0 = blockIdx.y*128, n0 = blockIdx.x*128;

    const unsigned short* srcs[4] = {
        g_Xhi + (size_t)m0*1024,
        g_Xlo + (size_t)m0*1024,
        g_Whi[layer] + (size_t)n0*1024,
        g_Wlo[layer] + (size_t)n0*1024
    };

    auto prefetch = [&](int kc, int stg){
        unsigned sb = sbase + stg*STAGE_B;
        #pragma unroll
        for (int it = 0; it < 8; ++it){
            int i = it*256 + tid;
            int p = i >> 9, rem = i & 511;
            int row = rem >> 2, c = rem & 3;
            unsigned sa = sb + p*PLANE_B + row*80 + c*16;
            const void* ga = srcs[p] + (size_t)row*1024 + kc*32 + c*8;
            asm volatile("cp.async.cg.shared.global [%0], [%1], 16;" :: "r"(sa), "l"(ga) : "memory");
        }
        asm volatile("cp.async.commit_group;" ::: "memory");
    };

    int wm = wid >> 1, wn = wid & 1;
    float d[2][8][4];
    #pragma unroll
    for (int mi=0;mi<2;++mi)
        #pragma unroll
        for (int ni=0;ni<8;++ni)
            #pragma unroll
            for (int q=0;q<4;++q) d[mi][ni][q] = 0.f;

    prefetch(0, 0);

    for (int kt = 0; kt < 32; ++kt){
        int stg = kt & 1;
        asm volatile("cp.async.wait_group 0;" ::: "memory");
        __syncthreads();
        if (kt + 1 < 32) prefetch(kt + 1, stg ^ 1);

        unsigned sb  = sbase + stg*STAGE_B;
        unsigned aHi = sb,            aLo = sb + PLANE_B;
        unsigned bHi = sb + 2*PLANE_B, bLo = sb + 3*PLANE_B;

        #pragma unroll
        for (int kh = 0; kh < 2; ++kh){
            unsigned Ah[2][4], Al[2][4];
            #pragma unroll
            for (int mi = 0; mi < 2; ++mi){
                int row = wm*32 + mi*16 + (lane & 15);
                int ch  = kh*2 + (lane >> 4);
                unsigned off = row*80 + ch*16;
                LDSM4(Ah[mi], aHi + off);
                LDSM4(Al[mi], aLo + off);
            }
            unsigned Bh[4][4], Bl[4][4];
            #pragma unroll
            for (int pr = 0; pr < 4; ++pr){
                int row = wn*64 + pr*16 + (lane & 7) + ((lane >> 4) << 3);
                int ch  = kh*2 + ((lane >> 3) & 1);
                unsigned off = row*80 + ch*16;
                LDSM4(Bh[pr], bHi + off);
                LDSM4(Bl[pr], bLo + off);
            }
            #pragma unroll
            for (int mi = 0; mi < 2; ++mi){
                #pragma unroll
                for (int pr = 0; pr < 4; ++pr){
                    MMA16816(d[mi][2*pr],   Ah[mi], Bh[pr][0], Bh[pr][1]);
                    MMA16816(d[mi][2*pr],   Ah[mi], Bl[pr][0], Bl[pr][1]);
                    MMA16816(d[mi][2*pr],   Al[mi], Bh[pr][0], Bh[pr][1]);
                    MMA16816(d[mi][2*pr+1], Ah[mi], Bh[pr][2], Bh[pr][3]);
                    MMA16816(d[mi][2*pr+1], Ah[mi], Bl[pr][2], Bl[pr][3]);
                    MMA16816(d[mi][2*pr+1], Al[mi], Bh[pr][2], Bh[pr][3]);
                }
            }
        }
    }

    int qr = lane >> 2, qc = lane & 3;
    #pragma unroll
    for (int mi = 0; mi < 2; ++mi){
        #pragma unroll
        for (int ni = 0; ni < 8; ++ni){
            int col = n0 + wn*64 + ni*8 + qc*2;
            float2 bq = *(const float2*)&g_biasG[layer][col];
            int r0 = m0 + wm*32 + mi*16 + qr;
            float2 v0 = make_float2(d[mi][ni][0] + bq.x, d[mi][ni][1] + bq.y);
            *(float2*)&g_G[(size_t)r0*NG + col] = v0;
            float2 v1 = make_float2(d[mi][ni][2] + bq.x, d[mi][ni][3] + bq.y);
            *(float2*)&g_G[(size_t)(r0+8)*NG + col] = v1;
        }
    }
}

// ------------------------ persistent BiLSTM recurrence (fused fw+bw, per-term chains) ------------------------
// R13 structure verbatim (best: 17.27ms) with ONE change: d0/d1 split into
// per-term accumulators (HH/HL/LH) -> 6 parallel 16-deep HMMA chains instead
// of two 48-deep chains.
#define R2_PH(h)   ((h)*33280)
#define R2_GP(h)   (66560 + (h)*4096)
#define R2_C(h)    (74752 + (h)*512)
#define R2_SMEM    75776

__global__ void __launch_bounds__(256) k_recur2(const float* __restrict__ whh, int layer, int outparity,
                                                int writeF32, int writePlanes){
    extern __shared__ char smem[];
    unsigned sb = smem_u32(smem);
    int tid = threadIdx.x;
    int half = tid >> 7;                 // 0 = fw, 1 = bw
    int htid = tid & 127;
    int hwid = htid >> 5;                // 0..3 within half
    int lane = tid & 31;
    int kw = hwid & 1, nw = hwid >> 1;   // K-half, row-half
    int dir = half;
    int bid = blockIdx.x;
    int j0 = bid*8;

    unsigned phBase = sb + R2_PH(half);          // PHI = phBase, PLO = phBase+16640
    float* sGp = (float*)(smem + R2_GP(half));
    float* sC  = (float*)(smem + R2_C(half));

    // ---- stage Whh (two 16-row chunks through h-plane region) + preload B frags ----
    unsigned Bh[16][4], Bl[16][4];
    for (int c = 0; c < 2; ++c){
        for (int i = htid; i < 2048; i += 128){      // 16 rows x 128 float4
            int row = i >> 7;
            int k4  = (i & 127) * 4;
            int grow = c*16 + row;
            int g = grow >> 3, jj = grow & 7;
            float4 w = *(const float4*)&whh[(((size_t)(layer*2+dir))*2048 + g*512 + j0 + jj)*512 + k4];
            unsigned short h0,l0,h1,l1,h2,l2,h3,l3;
            split_bf(w.x,h0,l0); split_bf(w.y,h1,l1); split_bf(w.z,h2,l2); split_bf(w.w,h3,l3);
            *(uint2*)(smem + R2_PH(half) + row*1040 + k4*2) =
                make_uint2((unsigned)h0 | ((unsigned)h1<<16), (unsigned)h2 | ((unsigned)h3<<16));
            *(uint2*)(smem + R2_PH(half) + 16640 + row*1040 + k4*2) =
                make_uint2((unsigned)l0 | ((unsigned)l1<<16), (unsigned)l2 | ((unsigned)l3<<16));
        }
        __syncthreads();
        if (nw == c){
            int rowB = (lane & 7) + ((lane >> 4) << 3);   // chunk-local 0..15
            int chB  = (lane >> 3) & 1;
            #pragma unroll
            for (int kt = 0; kt < 16; ++kt){
                int ktile = kw*16 + kt;
                unsigned off = rowB*1040 + ktile*32 + chB*16;
                LDSM4(Bh[kt], phBase + off);
                LDSM4(Bl[kt], phBase + 16640 + off);
            }
        }
        __syncthreads();
    }
    if (htid < 128) sC[htid] = 0.f;
    __syncthreads();

    // ---- cell-thread state (all 128 half-threads) ----
    int b2c = htid & 15, jj2c = htid >> 4;
    int colc = dir*2048 + j0 + jj2c;
    float gReg[4];
    {
        int t0 = dir ? (T_-1) : 0;
        #pragma unroll
        for (int g2 = 0; g2 < 4; ++g2)
            gReg[g2] = g_G[(size_t)(t0*16 + b2c)*NG + colc + g2*512];
    }

    float* xout = g_xbuf[outparity];
    unsigned* cnt = &g_cnt[dir][0];
    int offA_row = (lane & 15)*1040 + (lane >> 4)*16;
    int barid = 1 + half;

    for (int s = 0; s < T_; ++s){
        // stage packed h -> bf16 planes (this half's direction)
        const unsigned* hin = g_hPk[dir][s & 1];
        #pragma unroll
        for (int it = 0; it < 16; ++it){
            int i = it*128 + htid;                   // 0..2047 uint4
            int b = i >> 7, jq = (i & 127) * 4;
            uint4 v = __ldcg((const uint4*)&hin[b*512 + jq]);
            unsigned hiAB = __byte_perm(v.x, v.y, 0x7632);
            unsigned hiCD = __byte_perm(v.z, v.w, 0x7632);
            unsigned loAB = __byte_perm(v.x, v.y, 0x5410);
            unsigned loCD = __byte_perm(v.z, v.w, 0x5410);
            *(uint2*)(smem + R2_PH(half) + b*1040 + jq*2) = make_uint2(hiAB, hiCD);
            *(uint2*)(smem + R2_PH(half) + 16640 + b*1040 + jq*2) = make_uint2(loAB, loCD);
        }
        asm volatile("bar.sync %0, 128;" :: "r"(barid) : "memory");

        // MMA: 3-term split, K=256 per warp, n=16 rows per warp.
        // Six independent accumulator chains (16-deep each).
        float d0HH[4] = {0.f,0.f,0.f,0.f}, d0HL[4] = {0.f,0.f,0.f,0.f}, d0LH[4] = {0.f,0.f,0.f,0.f};
        float d1HH[4] = {0.f,0.f,0.f,0.f}, d1HL[4] = {0.f,0.f,0.f,0.f}, d1LH[4] = {0.f,0.f,0.f,0.f};
        #pragma unroll
        for (int kt = 0; kt < 16; ++kt){
            int ktile = kw*16 + kt;
            unsigned offA = offA_row + ktile*32;
            unsigned Ah[4], Al[4];
            LDSM4(Ah, phBase + offA);
            LDSM4(Al, phBase + 16640 + offA);
            MMA16816(d0HH, Ah, Bh[kt][0], Bh[kt][1]);
            MMA16816(d0HL, Ah, Bl[kt][0], Bl[kt][1]);
            MMA16816(d0LH, Al, Bh[kt][0], Bh[kt][1]);
            MMA16816(d1HH, Ah, Bh[kt][2], Bh[kt][3]);
            MMA16816(d1HL, Ah, Bl[kt][2], Bl[kt][3]);
            MMA16816(d1LH, Al, Bh[kt][2], Bh[kt][3]);
        }
        float d0[4], d1[4];
        #pragma unroll
        for (int q = 0; q < 4; ++q){
            d0[q] = d0HH[q] + d0HL[q] + d0LH[q];
            d1[q] = d1HH[q] + d1HL[q] + d1LH[q];
        }
        {
            int qr = lane >> 2, qc = lane & 3;
            int row0 = nw*16 + qc*2, row1 = nw*16 + 8 + qc*2;
            *(float2*)&sGp[(kw*16+qr)*32 + row0]   = make_float2(d0[0], d0[1]);
            *(float2*)&sGp[(kw*16+qr+8)*32 + row0] = make_float2(d0[2], d0[3]);
            *(float2*)&sGp[(kw*16+qr)*32 + row1]   = make_float2(d1[0], d1[1]);
            *(float2*)&sGp[(kw*16+qr+8)*32 + row1] = make_float2(d1[2], d1[3]);
        }
        asm volatile("bar.sync %0, 128;" :: "r"(barid) : "memory");

        // cell update (all 128 half-threads)
        float hval; size_t mo; unsigned hh, hl;
        {
            float ng[4] = {0.f,0.f,0.f,0.f};
            if (s+1 < T_){
                int tn = dir ? (T_-2 - s) : (s+1);
                #pragma unroll
                for (int g2 = 0; g2 < 4; ++g2)
                    ng[g2] = g_G[(size_t)(tn*16 + b2c)*NG + colc + g2*512];
            }
            float acc4[4];
            #pragma unroll
            for (int g2 = 0; g2 < 4; ++g2){
                int row = g2*8 + jj2c;
                float sd = sGp[(0*16 + b2c)*32 + row] + sGp[(1*16 + b2c)*32 + row];
                acc4[g2] = gReg[g2] + sd;
            }
            float c = sigf_fast(acc4[1])*sC[htid] + sigf_fast(acc4[0])*tanh_fast(acc4[2]);
            sC[htid] = c;
            hval = sigf_fast(acc4[3])*tanh_fast(c);
            __nv_bfloat16 hb = __float2bfloat16(hval);
            hh = __bfloat16_as_ushort(hb);
            hl = __bfloat16_as_ushort(__float2bfloat16(hval - __bfloat162float(hb)));
            g_hPk[dir][(s+1)&1][b2c*512 + j0 + jj2c] = (hh << 16) | hl;
            int t2 = dir ? (T_-1 - s) : s;
            mo = (size_t)(t2*16 + b2c)*1024 + dir*512 + j0 + jj2c;
            gReg[0] = ng[0]; gReg[1] = ng[1]; gReg[2] = ng[2]; gReg[3] = ng[3];
        }
        asm volatile("bar.sync %0, 128;" :: "r"(barid) : "memory");
        if (htid == 0){
            asm volatile("red.release.gpu.global.add.u32 [%0], %1;"
                         :: "l"(&cnt[s]), "r"(1u) : "memory");
        }
        // deferred next-layer output stores (outside the release chain)
        {
            if (writeF32) xout[mo] = hval;
            if (writePlanes){
                g_Xhi[mo] = (unsigned short)hh;
                g_Xlo[mo] = (unsigned short)hl;
            }
        }
        if (htid == 0){
            unsigned v;
            do {
                asm volatile("ld.acquire.gpu.global.u32 %0, [%1];"
                             : "=r"(v) : "l"(&cnt[s]) : "memory");
            } while (v < 64u);
        }
        asm volatile("bar.sync %0, 128;" :: "r"(barid) : "memory");
    }
}

// ------------------------ classifier ------------------------
__global__ void __launch_bounds__(256) k_cls(const float* __restrict__ cls_w,
                                             const float* __restrict__ cls_b, int parity){
    __shared__ float sW[L_][1024];
    __shared__ float sB[L_];
    int tid = threadIdx.x;
    for (int i = tid; i < L_*1024; i += 256) ((float*)sW)[i] = cls_w[i];
    if (tid < L_) sB[tid] = cls_b[tid];
    __syncthreads();
    int m = blockIdx.x*256 + tid;
    const float* xr = &g_xbuf[parity][(size_t)m*1024];
    float acc[L_];
    #pragma unroll
    for (int l=0;l<L_;l++) acc[l] = sB[l];
    for (int k = 0; k < 1024; k += 4){
        float4 xv = *(const float4*)&xr[k];
        #pragma unroll
        for (int l=0;l<L_;l++){
            float4 wv = *(const float4*)&sW[l][k];
            acc[l] += xv.x*wv.x + xv.y*wv.y + xv.z*wv.z + xv.w*wv.w;
        }
    }
    #pragma unroll
    for (int l=0;l<L_;l++) g_logits[m*L_ + l] = acc[l];
}

// ------------------------ CRF NLL (one block) ------------------------
__global__ void __launch_bounds__(128) k_crf(const int* __restrict__ att, const int* __restrict__ lab,
                                             const float* __restrict__ startv, const float* __restrict__ endv,
                                             const float* __restrict__ trans, float* __restrict__ out){
    __shared__ float sT[36], sS[6], sE[6];
    __shared__ float sAl[16][6];
    __shared__ float sNum[16], sLoss[16];
    int tid = threadIdx.x;
    if (tid < 36) sT[tid] = trans[tid];
    if (tid < 6){ sS[tid] = startv[tid]; sE[tid] = endv[tid]; }
    __syncthreads();

    bool isDen = tid < 96;
    bool isNum = (tid >= 96) && (tid < 112);
    int b = isDen ? tid/6 : tid-96;
    int j = tid % 6;

    float score = 0.f; int prev = 0;
    if (isDen) sAl[b][j] = sS[j] + g_logits[b*L_ + j];
    if (isNum){
        int l0 = lab[b*T_];
        int t0 = (l0 == -100) ? 0 : l0;
        score = sS[t0] + g_logits[b*L_ + t0];
        prev = t0;
    }
    __syncthreads();

    for (int t = 1; t < T_; ++t){
        float nxt = 0.f; bool mk = false;
        if (isDen){
            mk = (att[b*T_ + t] != 0) && (lab[b*T_ + t] != -100);
            float e = g_logits[(t*16 + b)*L_ + j];
            float mx = -1e30f;
            #pragma unroll
            for (int i2=0;i2<6;i2++) mx = fmaxf(mx, sAl[b][i2] + sT[i2*6+j]);
            float ss = 0.f;
            #pragma unroll
            for (int i2=0;i2<6;i2++) ss += expf(sAl[b][i2] + sT[i2*6+j] - mx);
            nxt = mx + logf(ss) + e;
        } else if (isNum){
            int lb = lab[b*T_ + t];
            bool m = (att[b*T_ + t] != 0) && (lb != -100);
            int tt = (lb == -100) ? 0 : lb;
            if (m){
                score += sT[prev*6 + tt] + g_logits[(t*16 + b)*L_ + tt];
                prev = tt;
            }
        }
        __syncthreads();
        if (isDen && mk) sAl[b][j] = nxt;
        __syncthreads();
    }

    if (isNum) sNum[b] = score + sE[prev];
    __syncthreads();
    if (tid < 16){
        float mx = -1e30f;
        #pragma unroll
        for (int jj=0;jj<6;jj++) mx = fmaxf(mx, sAl[tid][jj] + sE[jj]);
        float ss = 0.f;
        #pragma unroll
        for (int jj=0;jj<6;jj++) ss += expf(sAl[tid][jj] + sE[jj] - mx);
        float den = mx + logf(ss);
        sLoss[tid] = den - sNum[tid];
    }
    __syncthreads();
    if (tid == 0){
        float s = 0.f;
        for (int i=0;i<16;i++) s += sLoss[i];
        out[0] = s / 16.f;
    }
}

// ------------------------ launch ------------------------
extern "C" void kernel_launch(void* const* d_in, const int* in_sizes, int n_in,
                              void* d_out, int out_size){
    const float* emb    = (const float*)d_in[0];
    const int*   att    = (const int*)  d_in[1];
    const int*   lab    = (const int*)  d_in[2];
    const float* conv_w = (const float*)d_in[3];
    const float* conv_b = (const float*)d_in[4];
    const float* bn_g   = (const float*)d_in[5];
    const float* bn_b   = (const float*)d_in[6];
    const float* bn_m   = (const float*)d_in[7];
    const float* bn_v   = (const float*)d_in[8];
    const float* wih    = (const float*)d_in[9];
    const float* whh    = (const float*)d_in[10];
    const float* bih    = (const float*)d_in[11];
    const float* bhh    = (const float*)d_in[12];
    const float* cls_w  = (const float*)d_in[13];
    const float* cls_b  = (const float*)d_in[14];
    const float* crf_s  = (const float*)d_in[15];
    const float* crf_e  = (const float*)d_in[16];
    const float* crf_t  = (const float*)d_in[17];
    float* out = (float*)d_out;

    cudaFuncSetAttribute(k_recur2, cudaFuncAttributeMaxDynamicSharedMemorySize, R2_SMEM);
    cudaFuncSetAttribute(k_gate,   cudaFuncAttributeMaxDynamicSharedMemorySize, GT_SMEM);
    cudaFuncSetAttribute(k_convT,  cudaFuncAttributeMaxDynamicSharedMemorySize, GT_SMEM);

    k_cvt_e <<<B_*T_*E_/256, 256>>>(emb);
    k_cvt_cw<<<C_*KC_/256, 256>>>(conv_w);
    k_cvt_w <<<3*NG*KI/256, 256>>>(wih);
    k_pack_small<<<48, 256>>>(bih, bhh, bn_g, bn_b, bn_m, bn_v, conv_b);

    k_convT<<<dim3(C_/128, M_/128), 256, GT_SMEM>>>();

    for (int l = 0; l < 3; ++l){
        int outpar = (l + 1) & 1;
        int wF32    = (l == 2) ? 1 : 0;
        int wPlanes = (l == 2) ? 0 : 1;
        k_gate<<<dim3(NG/128, M_/128), 256, GT_SMEM>>>(l);
        k_reset<<<128, 256>>>();
        k_recur2<<<64, 256, R2_SMEM>>>(whh, l, outpar, wF32, wPlanes);
    }

    k_cls<<<M_/256, 256>>>(cls_w, cls_b, 1);
    k_crf<<<1, 128>>>(att, lab, crf_s, crf_e, crf_t, out);
}